// round 13
// baseline (speedup 1.0000x reference)
#include <cuda_runtime.h>

#define BB   32
#define DIMC 512
#define CC   128
#define WSZ  14
#define NN   196
#define NHD  4
#define HD   32
#define HIN  56

// Scratch (device globals; no runtime allocation)
__device__ float g_q[BB * NHD * NN * HD];  // [B][H][N][D] (pre-scaled via wT)
__device__ float g_k[BB * NHD * NN * HD];
__device__ float g_v[BB * NHD * NN * HD];
__device__ float g_ot[BB * CC * NN];       // attention output TRANSPOSED [B][C][N]
__device__ float g_wf[DIMC * CC];          // fused convout@proj weight [512][128]
__device__ float g_bf[DIMC];               // fused bias
__device__ float g_wqkvT[CC * 3 * CC];     // qkv weight transposed [c][j], q rows pre-scaled

// ---------------------------------------------------------------------------
// K0: prep. blocks 0..511: Wf = convout_w @ proj_w, bf = convout_w@proj_b + cb
//          blocks 512..639: transpose qkv_w -> [c][j], q rows pre-scaled
// grid 640, block 384
// ---------------------------------------------------------------------------
__global__ void prep_kernel(const float* __restrict__ cw,
                            const float* __restrict__ cb,
                            const float* __restrict__ pw,
                            const float* __restrict__ pb,
                            const float* __restrict__ qkvw)
{
    int t = threadIdx.x;
    if (blockIdx.x < DIMC) {
        int oc = blockIdx.x;
        __shared__ float row[CC];
        __shared__ float red[CC];
        if (t < CC) row[t] = cw[oc * CC + t];
        __syncthreads();
        if (t < CC) {
            float acc = 0.0f;
            for (int k = 0; k < CC; k++) acc += row[k] * pw[k * CC + t];
            g_wf[oc * CC + t] = acc;
            red[t] = row[t] * pb[t];
        }
        __syncthreads();
        for (int s = 64; s > 0; s >>= 1) {
            if (t < s) red[t] += red[t + s];
            __syncthreads();
        }
        if (t == 0) g_bf[oc] = red[0] + cb[oc];
    } else {
        int c = blockIdx.x - DIMC;      // 0..127
        float v = qkvw[t * CC + c];
        if (t < CC) v *= 0.17677669529663687f;
        g_wqkvT[c * 384 + t] = v;
    }
}

// ---------------------------------------------------------------------------
// K1: FUSED grouped conv 4x4 s4 + BN + ReLU6 + qkv GEMM.
// grid (7 token-tiles, B), block 448.
// ---------------------------------------------------------------------------
#define TS_STRIDE 132

__global__ void __launch_bounds__(448, 2)
convqkv_kernel(const float* __restrict__ x,
               const float* __restrict__ cw,
               const float* __restrict__ cb,
               const float* __restrict__ gamma,
               const float* __restrict__ beta,
               const float* __restrict__ mean,
               const float* __restrict__ var)
{
    __shared__ float ws[CC * 64];          // 32KB conv weights
    __shared__ float bnsc[CC], bnsh[CC];
    __shared__ float ts[28 * TS_STRIDE];   // token tile, padded

    int tile = blockIdx.x, b = blockIdx.y;
    int t = threadIdx.x;

    for (int idx = t; idx < CC * 64 / 4; idx += 448)
        ((float4*)ws)[idx] = ((const float4*)cw)[idx];
    if (t < CC) {
        float sc = gamma[t] * rsqrtf(var[t] + 1e-5f);
        bnsc[t] = sc;
        bnsh[t] = cb[t] * sc + beta[t] - mean[t] * sc;
    }
    __syncthreads();

    // ---- Phase 1: conv ----
    {
        int n = t % 28, cl = t / 28;       // cl 0..15
        int oh = tile * 2 + n / WSZ, ow = n % WSZ;
        const float* xb = x + (size_t)b * DIMC * HIN * HIN + (4 * oh) * HIN + 4 * ow;
#pragma unroll
        for (int p = 0; p < 8; p++) {
            int c = p * 16 + cl;
            float acc = 0.0f;
            const float* wp0 = ws + c * 64;
            const float* xc = xb + (size_t)(4 * c) * HIN * HIN;
#pragma unroll
            for (int i = 0; i < 4; i++) {
                const float* xp = xc + (size_t)i * HIN * HIN;
#pragma unroll
                for (int kh = 0; kh < 4; kh++) {
                    float4 v = *(const float4*)(xp + kh * HIN);
                    const float* wp = wp0 + i * 16 + kh * 4;
                    acc += v.x * wp[0] + v.y * wp[1] + v.z * wp[2] + v.w * wp[3];
                }
            }
            acc = acc * bnsc[c] + bnsh[c];
            ts[n * TS_STRIDE + c] = fminf(fmaxf(acc, 0.0f), 6.0f);
        }
    }
    __syncthreads();

    // ---- Phase 2: qkv GEMM (threads 0..383) ----
    if (t < 384) {
        int jp = (t % 192) * 2;
        int rg = t / 192;
        int n0 = tile * 28;

        float acc0[14], acc1[14];
#pragma unroll
        for (int r = 0; r < 14; r++) { acc0[r] = 0.0f; acc1[r] = 0.0f; }

        const float* tsb = ts + (rg * 14) * TS_STRIDE;
        for (int cq = 0; cq < 32; cq++) {
            int c = cq * 4;
            float2 w0 = *(const float2*)(g_wqkvT + (size_t)(c + 0) * 384 + jp);
            float2 w1 = *(const float2*)(g_wqkvT + (size_t)(c + 1) * 384 + jp);
            float2 w2 = *(const float2*)(g_wqkvT + (size_t)(c + 2) * 384 + jp);
            float2 w3 = *(const float2*)(g_wqkvT + (size_t)(c + 3) * 384 + jp);
#pragma unroll
            for (int r = 0; r < 14; r++) {
                float4 tv = *(const float4*)(tsb + r * TS_STRIDE + c);
                acc0[r] += tv.x * w0.x + tv.y * w1.x + tv.z * w2.x + tv.w * w3.x;
                acc1[r] += tv.x * w0.y + tv.y * w1.y + tv.z * w2.y + tv.w * w3.y;
            }
        }

#pragma unroll
        for (int which = 0; which < 2; which++) {
            int j = jp + which;
            int s = j / CC, rem = j % CC;
            int h = rem / HD, d = rem % HD;
            float* dst = (s == 0) ? g_q : ((s == 1) ? g_k : g_v);
            dst += (((size_t)(b * NHD + h)) * NN + n0 + rg * 14) * HD + d;
            const float* a = which ? acc1 : acc0;
#pragma unroll
            for (int r = 0; r < 14; r++) dst[r * HD] = a[r];
        }
    }
}

// ---------------------------------------------------------------------------
// K2: attention. grid (4 q-tiles, 128 bh), block 224.
// ---------------------------------------------------------------------------
#define KV_STRIDE 36
#define ATTN_SMEM ((196 * KV_STRIDE * 2 + 729) * 4)

__global__ void attn_kernel(const float* __restrict__ rpb)
{
    extern __shared__ float sm[];
    float* ks_s  = sm;
    float* vs_s  = sm + 196 * KV_STRIDE;
    float* rpb_s = sm + 196 * KV_STRIDE * 2;

    int qt = blockIdx.x;
    int bh = blockIdx.y;
    int h  = bh & 3;
    int t  = threadIdx.x;
    int qi = t >> 2, ks = t & 3;
    bool active = (qi < 49);
    int q = active ? (qt * 49 + qi) : 195;

    const float* kb = g_k + (size_t)bh * NN * HD;
    const float* vb = g_v + (size_t)bh * NN * HD;
    for (int idx = t; idx < 196 * 8; idx += 224) {
        int r = idx >> 3, qd = idx & 7;
        *(float4*)(ks_s + r * KV_STRIDE + qd * 4) = ((const float4*)(kb + r * HD))[qd];
        *(float4*)(vs_s + r * KV_STRIDE + qd * 4) = ((const float4*)(vb + r * HD))[qd];
    }
    for (int i = t; i < 729; i += 224) rpb_s[i] = rpb[i * NHD + h];
    __syncthreads();

    float4 q4[8];
    const float4* qp = (const float4*)(g_q + ((size_t)bh * NN + q) * HD);
#pragma unroll
    for (int i = 0; i < 8; i++) q4[i] = qp[i];
    int r1 = q / WSZ, c1 = q % WSZ;

    float mx = -1e30f, sum = 0.0f;
    float acc[32];
#pragma unroll
    for (int d = 0; d < 32; d++) acc[d] = 0.0f;

    int base_m = ks * 49;
    for (int g = 0; g < 7; g++) {
        int m0 = base_m + g * 7;
        float s[7];
#pragma unroll
        for (int u = 0; u < 7; u++) {
            const float* kr = ks_s + (m0 + u) * KV_STRIDE;
            float sv = 0.0f;
#pragma unroll
            for (int qd = 0; qd < 8; qd++) {
                float4 kv = *(const float4*)(kr + qd * 4);
                sv += q4[qd].x * kv.x + q4[qd].y * kv.y + q4[qd].z * kv.z + q4[qd].w * kv.w;
            }
            int m = m0 + u;
            int r2 = m / WSZ, c2 = m % WSZ;
            s[u] = sv + rpb_s[(r1 - r2 + 13) * 27 + (c1 - c2 + 13)];
        }
        float gm = s[0];
#pragma unroll
        for (int u = 1; u < 7; u++) gm = fmaxf(gm, s[u]);
        float nm = fmaxf(mx, gm);
        float corr = __expf(mx - nm);
        mx = nm;
        float ps = 0.0f;
#pragma unroll
        for (int u = 0; u < 7; u++) { s[u] = __expf(s[u] - nm); ps += s[u]; }
        sum = sum * corr + ps;

#pragma unroll
        for (int qd = 0; qd < 8; qd++) {
            float4 vv[7];
#pragma unroll
            for (int u = 0; u < 7; u++)
                vv[u] = *(const float4*)(vs_s + (m0 + u) * KV_STRIDE + qd * 4);
#pragma unroll
            for (int z = 0; z < 4; z++) {
                float a = acc[qd * 4 + z] * corr;
#pragma unroll
                for (int u = 0; u < 7; u++)
                    a += s[u] * ((const float*)&vv[u])[z];
                acc[qd * 4 + z] = a;
            }
        }
    }

#pragma unroll
    for (int off = 1; off <= 2; off <<= 1) {
        float m2 = __shfl_xor_sync(0xffffffffu, mx, off);
        float s2 = __shfl_xor_sync(0xffffffffu, sum, off);
        float nm = fmaxf(mx, m2);
        float ca = __expf(mx - nm);
        float cb2 = __expf(m2 - nm);
        sum = sum * ca + s2 * cb2;
#pragma unroll
        for (int d = 0; d < 32; d++)
            acc[d] = acc[d] * ca + __shfl_xor_sync(0xffffffffu, acc[d], off) * cb2;
        mx = nm;
    }

    if (active) {
        float inv = 1.0f / sum;
        int b = bh >> 2;
#pragma unroll
        for (int jj = 0; jj < 8; jj++) {
            int c = h * HD + ks * 8 + jj;
            g_ot[((size_t)b * CC + c) * NN + q] = acc[ks * 8 + jj] * inv;
        }
    }
}

// ---------------------------------------------------------------------------
// K3: fused (proj∘convout) GEMM + bilinear x4 upsample, writes d_out.
// grid (16 oc-tiles, B), block 224.
// Phase A (t<196): GEMM into ms[32][197-pad], thread = 4 tokens x 8 oc.
// Phase B: separable upsample. Thread = (f = t%14 fixed 4 output cols,
//   cg = t/14 -> channels cg, cg+16). Step 1: column-interp into colexp[56]
//   registers (8 LDS + 4 lerps per src row). Step 2: output-row loop FULLY
//   UNROLLED with compile-time lr/hr/wr -> static reg indexing, zero LDS:
//   4 lerps + 1 coalesced STG.128 per output float4.
// ---------------------------------------------------------------------------
#define MS_STRIDE 197

__global__ void __launch_bounds__(224, 3) outup_kernel(float* __restrict__ out)
{
    __shared__ float wfs[32 * CC];       // 16KB
    __shared__ float bfs[32];
    __shared__ float ms[32 * MS_STRIDE]; // ~24.6KB
    __shared__ int   lo_s[HIN];
    __shared__ float w_s[HIN];

    int b = blockIdx.y;
    int oc0 = blockIdx.x * 32;
    int t = threadIdx.x;

    for (int idx = t; idx < 32 * CC / 4; idx += 224)
        ((float4*)wfs)[idx] = ((const float4*)(g_wf + (size_t)oc0 * CC))[idx];
    if (t < 32) bfs[t] = g_bf[oc0 + t];
    if (t < HIN) {
        float s = (float)(t * 13) / 55.0f;
        int lo = (int)s;
        lo_s[t] = lo;
        w_s[t] = s - (float)lo;
    }
    __syncthreads();

    // Phase A: GEMM (thread = 4 tokens x 8 oc), threads 0..195
    if (t < 196) {
        int ng = t % 49, ocg = t / 49;
        int n0 = ng * 4;
        float acc[32];
#pragma unroll
        for (int i = 0; i < 32; i++) acc[i] = 0.0f;

        const float* ob = g_ot + (size_t)b * CC * NN;
        for (int c = 0; c < CC; c++) {
            float4 ov = *(const float4*)(ob + (size_t)c * NN + n0);
#pragma unroll
            for (int k = 0; k < 8; k++) {
                float w = wfs[(ocg * 8 + k) * CC + c];
                acc[k * 4 + 0] += w * ov.x;
                acc[k * 4 + 1] += w * ov.y;
                acc[k * 4 + 2] += w * ov.z;
                acc[k * 4 + 3] += w * ov.w;
            }
        }
#pragma unroll
        for (int k = 0; k < 8; k++) {
            float bv = bfs[ocg * 8 + k];
#pragma unroll
            for (int z = 0; z < 4; z++)
                ms[(ocg * 8 + k) * MS_STRIDE + n0 + z] = acc[k * 4 + z] + bv;
        }
    }
    __syncthreads();

    // Phase B: separable upsample
    {
        int f  = t % 14;            // float4 index within output row (fixed)
        int cg = t / 14;            // 0..15 -> channels cg, cg+16

        int   lcz[4], hcz[4];
        float wcz[4];
#pragma unroll
        for (int z = 0; z < 4; z++) {
            int P = f * 4 + z;
            int lc = lo_s[P];
            lcz[z] = lc;
            hcz[z] = (lc + 1 < 14) ? lc + 1 : 13;
            wcz[z] = w_s[P];
        }

        float* obb = out + ((size_t)b * DIMC + oc0) * HIN * HIN;
#pragma unroll
        for (int cc2 = 0; cc2 < 2; cc2++) {
            int ch = cg + cc2 * 16;
            const float* src = ms + ch * MS_STRIDE;

            // Step 1: column interpolation into registers
            float colexp[56];
#pragma unroll
            for (int j = 0; j < 14; j++) {
                const float* sr = src + j * WSZ;
#pragma unroll
                for (int z = 0; z < 4; z++) {
                    float a = sr[lcz[z]];
                    float bq = sr[hcz[z]];
                    colexp[j * 4 + z] = a + wcz[z] * (bq - a);
                }
            }

            // Step 2: row interpolation, compile-time coefficients
            float* ocb = obb + (size_t)ch * (HIN * HIN) + f * 4;
#pragma unroll
            for (int O = 0; O < 56; O++) {
                const int lr = (O * 13) / 55;
                const int hr = (lr + 1 < 14) ? lr + 1 : 13;
                const float wr = (float)(O * 13 - lr * 55) * (1.0f / 55.0f);
                float4 v;
#pragma unroll
                for (int z = 0; z < 4; z++) {
                    float a  = colexp[lr * 4 + z];
                    float bq = colexp[hr * 4 + z];
                    ((float*)&v)[z] = a + wr * (bq - a);
                }
                *(float4*)(ocb + O * HIN) = v;
            }
        }
    }
}

// ---------------------------------------------------------------------------
extern "C" void kernel_launch(void* const* d_in, const int* in_sizes, int n_in,
                              void* d_out, int out_size)
{
    (void)in_sizes; (void)n_in; (void)out_size;
    const float* x        = (const float*)d_in[0];
    const float* conv_w   = (const float*)d_in[1];
    const float* conv_b   = (const float*)d_in[2];
    const float* bn_gamma = (const float*)d_in[3];
    const float* bn_beta  = (const float*)d_in[4];
    const float* bn_mean  = (const float*)d_in[5];
    const float* bn_var   = (const float*)d_in[6];
    const float* qkv_w    = (const float*)d_in[7];
    const float* proj_w   = (const float*)d_in[8];
    const float* proj_b   = (const float*)d_in[9];
    const float* rpb      = (const float*)d_in[10];
    const float* cvo_w    = (const float*)d_in[11];
    const float* cvo_b    = (const float*)d_in[12];
    float* out = (float*)d_out;

    cudaFuncSetAttribute(attn_kernel, cudaFuncAttributeMaxDynamicSharedMemorySize, ATTN_SMEM);

    prep_kernel<<<DIMC + CC, 384>>>(cvo_w, cvo_b, proj_w, proj_b, qkv_w);
    convqkv_kernel<<<dim3(7, BB), 448>>>(x, conv_w, conv_b, bn_gamma, bn_beta, bn_mean, bn_var);
    attn_kernel<<<dim3(4, BB * NHD), 224, ATTN_SMEM>>>(rpb);
    outup_kernel<<<dim3(16, BB), 224>>>(out);
}

// round 14
// speedup vs baseline: 1.0787x; 1.0787x over previous
#include <cuda_runtime.h>

#define BB   32
#define DIMC 512
#define CC   128
#define WSZ  14
#define NN   196
#define NHD  4
#define HD   32
#define HIN  56

// Scratch (device globals; no runtime allocation)
__device__ float g_q[BB * NHD * NN * HD];  // [B][H][N][D] (pre-scaled via wT)
__device__ float g_k[BB * NHD * NN * HD];
__device__ float g_v[BB * NHD * NN * HD];
__device__ float g_ot[BB * CC * NN];       // attention output TRANSPOSED [B][C][N]
__device__ float g_wf[DIMC * CC];          // fused convout@proj weight [512][128]
__device__ float g_bf[DIMC];               // fused bias
__device__ float g_wqkvT[CC * 3 * CC];     // qkv weight transposed [c][j], q rows pre-scaled

// ---------------------------------------------------------------------------
// K0: prep. blocks 0..511: Wf = convout_w @ proj_w, bf = convout_w@proj_b + cb
//          blocks 512..639: transpose qkv_w -> [c][j], q rows pre-scaled
// grid 640, block 384
// ---------------------------------------------------------------------------
__global__ void prep_kernel(const float* __restrict__ cw,
                            const float* __restrict__ cb,
                            const float* __restrict__ pw,
                            const float* __restrict__ pb,
                            const float* __restrict__ qkvw)
{
    int t = threadIdx.x;
    if (blockIdx.x < DIMC) {
        int oc = blockIdx.x;
        __shared__ float row[CC];
        __shared__ float red[CC];
        if (t < CC) row[t] = cw[oc * CC + t];
        __syncthreads();
        if (t < CC) {
            float acc = 0.0f;
            for (int k = 0; k < CC; k++) acc += row[k] * pw[k * CC + t];
            g_wf[oc * CC + t] = acc;
            red[t] = row[t] * pb[t];
        }
        __syncthreads();
        for (int s = 64; s > 0; s >>= 1) {
            if (t < s) red[t] += red[t + s];
            __syncthreads();
        }
        if (t == 0) g_bf[oc] = red[0] + cb[oc];
    } else {
        int c = blockIdx.x - DIMC;      // 0..127
        float v = qkvw[t * CC + c];
        if (t < CC) v *= 0.17677669529663687f;
        g_wqkvT[c * 384 + t] = v;
    }
}

// ---------------------------------------------------------------------------
// K1: FUSED grouped conv 4x4 s4 + BN + ReLU6 + qkv GEMM.
// grid (7 token-tiles, B), block 448.
// ---------------------------------------------------------------------------
#define TS_STRIDE 132

__global__ void __launch_bounds__(448, 2)
convqkv_kernel(const float* __restrict__ x,
               const float* __restrict__ cw,
               const float* __restrict__ cb,
               const float* __restrict__ gamma,
               const float* __restrict__ beta,
               const float* __restrict__ mean,
               const float* __restrict__ var)
{
    __shared__ float ws[CC * 64];          // 32KB conv weights
    __shared__ float bnsc[CC], bnsh[CC];
    __shared__ float ts[28 * TS_STRIDE];   // token tile, padded

    int tile = blockIdx.x, b = blockIdx.y;
    int t = threadIdx.x;

    for (int idx = t; idx < CC * 64 / 4; idx += 448)
        ((float4*)ws)[idx] = ((const float4*)cw)[idx];
    if (t < CC) {
        float sc = gamma[t] * rsqrtf(var[t] + 1e-5f);
        bnsc[t] = sc;
        bnsh[t] = cb[t] * sc + beta[t] - mean[t] * sc;
    }
    __syncthreads();

    // ---- Phase 1: conv ----
    {
        int n = t % 28, cl = t / 28;       // cl 0..15
        int oh = tile * 2 + n / WSZ, ow = n % WSZ;
        const float* xb = x + (size_t)b * DIMC * HIN * HIN + (4 * oh) * HIN + 4 * ow;
#pragma unroll
        for (int p = 0; p < 8; p++) {
            int c = p * 16 + cl;
            float acc = 0.0f;
            const float* wp0 = ws + c * 64;
            const float* xc = xb + (size_t)(4 * c) * HIN * HIN;
#pragma unroll
            for (int i = 0; i < 4; i++) {
                const float* xp = xc + (size_t)i * HIN * HIN;
#pragma unroll
                for (int kh = 0; kh < 4; kh++) {
                    float4 v = *(const float4*)(xp + kh * HIN);
                    const float* wp = wp0 + i * 16 + kh * 4;
                    acc += v.x * wp[0] + v.y * wp[1] + v.z * wp[2] + v.w * wp[3];
                }
            }
            acc = acc * bnsc[c] + bnsh[c];
            ts[n * TS_STRIDE + c] = fminf(fmaxf(acc, 0.0f), 6.0f);
        }
    }
    __syncthreads();

    // ---- Phase 2: qkv GEMM (threads 0..383) ----
    if (t < 384) {
        int jp = (t % 192) * 2;
        int rg = t / 192;
        int n0 = tile * 28;

        float acc0[14], acc1[14];
#pragma unroll
        for (int r = 0; r < 14; r++) { acc0[r] = 0.0f; acc1[r] = 0.0f; }

        const float* tsb = ts + (rg * 14) * TS_STRIDE;
        for (int cq = 0; cq < 32; cq++) {
            int c = cq * 4;
            float2 w0 = *(const float2*)(g_wqkvT + (size_t)(c + 0) * 384 + jp);
            float2 w1 = *(const float2*)(g_wqkvT + (size_t)(c + 1) * 384 + jp);
            float2 w2 = *(const float2*)(g_wqkvT + (size_t)(c + 2) * 384 + jp);
            float2 w3 = *(const float2*)(g_wqkvT + (size_t)(c + 3) * 384 + jp);
#pragma unroll
            for (int r = 0; r < 14; r++) {
                float4 tv = *(const float4*)(tsb + r * TS_STRIDE + c);
                acc0[r] += tv.x * w0.x + tv.y * w1.x + tv.z * w2.x + tv.w * w3.x;
                acc1[r] += tv.x * w0.y + tv.y * w1.y + tv.z * w2.y + tv.w * w3.y;
            }
        }

#pragma unroll
        for (int which = 0; which < 2; which++) {
            int j = jp + which;
            int s = j / CC, rem = j % CC;
            int h = rem / HD, d = rem % HD;
            float* dst = (s == 0) ? g_q : ((s == 1) ? g_k : g_v);
            dst += (((size_t)(b * NHD + h)) * NN + n0 + rg * 14) * HD + d;
            const float* a = which ? acc1 : acc0;
#pragma unroll
            for (int r = 0; r < 14; r++) dst[r * HD] = a[r];
        }
    }
}

// ---------------------------------------------------------------------------
// K2: attention. grid (4 q-tiles, 128 bh), block 224.
// ---------------------------------------------------------------------------
#define KV_STRIDE 36
#define ATTN_SMEM ((196 * KV_STRIDE * 2 + 729) * 4)

__global__ void attn_kernel(const float* __restrict__ rpb)
{
    extern __shared__ float sm[];
    float* ks_s  = sm;
    float* vs_s  = sm + 196 * KV_STRIDE;
    float* rpb_s = sm + 196 * KV_STRIDE * 2;

    int qt = blockIdx.x;
    int bh = blockIdx.y;
    int h  = bh & 3;
    int t  = threadIdx.x;
    int qi = t >> 2, ks = t & 3;
    bool active = (qi < 49);
    int q = active ? (qt * 49 + qi) : 195;

    const float* kb = g_k + (size_t)bh * NN * HD;
    const float* vb = g_v + (size_t)bh * NN * HD;
    for (int idx = t; idx < 196 * 8; idx += 224) {
        int r = idx >> 3, qd = idx & 7;
        *(float4*)(ks_s + r * KV_STRIDE + qd * 4) = ((const float4*)(kb + r * HD))[qd];
        *(float4*)(vs_s + r * KV_STRIDE + qd * 4) = ((const float4*)(vb + r * HD))[qd];
    }
    for (int i = t; i < 729; i += 224) rpb_s[i] = rpb[i * NHD + h];
    __syncthreads();

    float4 q4[8];
    const float4* qp = (const float4*)(g_q + ((size_t)bh * NN + q) * HD);
#pragma unroll
    for (int i = 0; i < 8; i++) q4[i] = qp[i];
    int r1 = q / WSZ, c1 = q % WSZ;

    float mx = -1e30f, sum = 0.0f;
    float acc[32];
#pragma unroll
    for (int d = 0; d < 32; d++) acc[d] = 0.0f;

    int base_m = ks * 49;
    for (int g = 0; g < 7; g++) {
        int m0 = base_m + g * 7;
        float s[7];
#pragma unroll
        for (int u = 0; u < 7; u++) {
            const float* kr = ks_s + (m0 + u) * KV_STRIDE;
            float sv = 0.0f;
#pragma unroll
            for (int qd = 0; qd < 8; qd++) {
                float4 kv = *(const float4*)(kr + qd * 4);
                sv += q4[qd].x * kv.x + q4[qd].y * kv.y + q4[qd].z * kv.z + q4[qd].w * kv.w;
            }
            int m = m0 + u;
            int r2 = m / WSZ, c2 = m % WSZ;
            s[u] = sv + rpb_s[(r1 - r2 + 13) * 27 + (c1 - c2 + 13)];
        }
        float gm = s[0];
#pragma unroll
        for (int u = 1; u < 7; u++) gm = fmaxf(gm, s[u]);
        float nm = fmaxf(mx, gm);
        float corr = __expf(mx - nm);
        mx = nm;
        float ps = 0.0f;
#pragma unroll
        for (int u = 0; u < 7; u++) { s[u] = __expf(s[u] - nm); ps += s[u]; }
        sum = sum * corr + ps;

#pragma unroll
        for (int qd = 0; qd < 8; qd++) {
            float4 vv[7];
#pragma unroll
            for (int u = 0; u < 7; u++)
                vv[u] = *(const float4*)(vs_s + (m0 + u) * KV_STRIDE + qd * 4);
#pragma unroll
            for (int z = 0; z < 4; z++) {
                float a = acc[qd * 4 + z] * corr;
#pragma unroll
                for (int u = 0; u < 7; u++)
                    a += s[u] * ((const float*)&vv[u])[z];
                acc[qd * 4 + z] = a;
            }
        }
    }

#pragma unroll
    for (int off = 1; off <= 2; off <<= 1) {
        float m2 = __shfl_xor_sync(0xffffffffu, mx, off);
        float s2 = __shfl_xor_sync(0xffffffffu, sum, off);
        float nm = fmaxf(mx, m2);
        float ca = __expf(mx - nm);
        float cb2 = __expf(m2 - nm);
        sum = sum * ca + s2 * cb2;
#pragma unroll
        for (int d = 0; d < 32; d++)
            acc[d] = acc[d] * ca + __shfl_xor_sync(0xffffffffu, acc[d], off) * cb2;
        mx = nm;
    }

    if (active) {
        float inv = 1.0f / sum;
        int b = bh >> 2;
#pragma unroll
        for (int jj = 0; jj < 8; jj++) {
            int c = h * HD + ks * 8 + jj;
            g_ot[((size_t)b * CC + c) * NN + q] = acc[ks * 8 + jj] * inv;
        }
    }
}

// ---------------------------------------------------------------------------
// K3: fused (proj∘convout) GEMM + bilinear x4 upsample, writes d_out.
// grid (16 oc-tiles, B), block 224.
// Phase A (t<196): GEMM into ms[32][197-pad], thread = 4 tokens x 8 oc.
// Phase B: separable upsample, TWO PASSES to keep colexp at 32 regs (no spill).
//   pass 0: src rows 0..7  -> output rows  0..27
//   pass 1: src rows 6..13 -> output rows 28..55
//   Row loop fully unrolled, compile-time lr/hr/wr -> static reg indexing.
// ---------------------------------------------------------------------------
#define MS_STRIDE 197

__global__ void outup_kernel(float* __restrict__ out)
{
    __shared__ float wfs[32 * CC];       // 16KB
    __shared__ float bfs[32];
    __shared__ float ms[32 * MS_STRIDE]; // ~24.6KB
    __shared__ int   lo_s[HIN];
    __shared__ float w_s[HIN];

    int b = blockIdx.y;
    int oc0 = blockIdx.x * 32;
    int t = threadIdx.x;

    for (int idx = t; idx < 32 * CC / 4; idx += 224)
        ((float4*)wfs)[idx] = ((const float4*)(g_wf + (size_t)oc0 * CC))[idx];
    if (t < 32) bfs[t] = g_bf[oc0 + t];
    if (t < HIN) {
        float s = (float)(t * 13) / 55.0f;
        int lo = (int)s;
        lo_s[t] = lo;
        w_s[t] = s - (float)lo;
    }
    __syncthreads();

    // Phase A: GEMM (thread = 4 tokens x 8 oc), threads 0..195
    if (t < 196) {
        int ng = t % 49, ocg = t / 49;
        int n0 = ng * 4;
        float acc[32];
#pragma unroll
        for (int i = 0; i < 32; i++) acc[i] = 0.0f;

        const float* ob = g_ot + (size_t)b * CC * NN;
        for (int c = 0; c < CC; c++) {
            float4 ov = *(const float4*)(ob + (size_t)c * NN + n0);
#pragma unroll
            for (int k = 0; k < 8; k++) {
                float w = wfs[(ocg * 8 + k) * CC + c];
                acc[k * 4 + 0] += w * ov.x;
                acc[k * 4 + 1] += w * ov.y;
                acc[k * 4 + 2] += w * ov.z;
                acc[k * 4 + 3] += w * ov.w;
            }
        }
#pragma unroll
        for (int k = 0; k < 8; k++) {
            float bv = bfs[ocg * 8 + k];
#pragma unroll
            for (int z = 0; z < 4; z++)
                ms[(ocg * 8 + k) * MS_STRIDE + n0 + z] = acc[k * 4 + z] + bv;
        }
    }
    __syncthreads();

    // Phase B: separable upsample, two half-passes (colexp stays 32 regs)
    {
        int f  = t % 14;            // float4 index within output row (fixed)
        int cg = t / 14;            // 0..15 -> channels cg, cg+16

        int   lcz[4], hcz[4];
        float wcz[4];
#pragma unroll
        for (int z = 0; z < 4; z++) {
            int P = f * 4 + z;
            int lc = lo_s[P];
            lcz[z] = lc;
            hcz[z] = (lc + 1 < 14) ? lc + 1 : 13;
            wcz[z] = w_s[P];
        }

        float* obb = out + ((size_t)b * DIMC + oc0) * HIN * HIN;
#pragma unroll
        for (int cc2 = 0; cc2 < 2; cc2++) {
            int ch = cg + cc2 * 16;
            const float* src = ms + ch * MS_STRIDE;
            float* ocb = obb + (size_t)ch * (HIN * HIN) + f * 4;

#pragma unroll
            for (int pass = 0; pass < 2; pass++) {
                const int jbase = pass ? 6 : 0;

                // Step 1: column interpolation for 8 src rows
                float colexp[32];
#pragma unroll
                for (int j = 0; j < 8; j++) {
                    const float* sr = src + (jbase + j) * WSZ;
#pragma unroll
                    for (int z = 0; z < 4; z++) {
                        float a  = sr[lcz[z]];
                        float bq = sr[hcz[z]];
                        colexp[j * 4 + z] = a + wcz[z] * (bq - a);
                    }
                }

                // Step 2: 28 output rows, compile-time coefficients
                const int Obase = pass * 28;
#pragma unroll
                for (int oo = 0; oo < 28; oo++) {
                    const int O  = Obase + oo;
                    const int lr = (O * 13) / 55;
                    const int hr = (lr + 1 < 14) ? lr + 1 : 13;
                    const float wr = (float)(O * 13 - lr * 55) * (1.0f / 55.0f);
                    const int lri = lr - jbase;      // 0..7 compile-time
                    const int hri = hr - jbase;
                    float4 v;
#pragma unroll
                    for (int z = 0; z < 4; z++) {
                        float a  = colexp[lri * 4 + z];
                        float bq = colexp[hri * 4 + z];
                        ((float*)&v)[z] = a + wr * (bq - a);
                    }
                    *(float4*)(ocb + O * HIN) = v;
                }
            }
        }
    }
}

// ---------------------------------------------------------------------------
extern "C" void kernel_launch(void* const* d_in, const int* in_sizes, int n_in,
                              void* d_out, int out_size)
{
    (void)in_sizes; (void)n_in; (void)out_size;
    const float* x        = (const float*)d_in[0];
    const float* conv_w   = (const float*)d_in[1];
    const float* conv_b   = (const float*)d_in[2];
    const float* bn_gamma = (const float*)d_in[3];
    const float* bn_beta  = (const float*)d_in[4];
    const float* bn_mean  = (const float*)d_in[5];
    const float* bn_var   = (const float*)d_in[6];
    const float* qkv_w    = (const float*)d_in[7];
    const float* proj_w   = (const float*)d_in[8];
    const float* proj_b   = (const float*)d_in[9];
    const float* rpb      = (const float*)d_in[10];
    const float* cvo_w    = (const float*)d_in[11];
    const float* cvo_b    = (const float*)d_in[12];
    float* out = (float*)d_out;

    cudaFuncSetAttribute(attn_kernel, cudaFuncAttributeMaxDynamicSharedMemorySize, ATTN_SMEM);

    prep_kernel<<<DIMC + CC, 384>>>(cvo_w, cvo_b, proj_w, proj_b, qkv_w);
    convqkv_kernel<<<dim3(7, BB), 448>>>(x, conv_w, conv_b, bn_gamma, bn_beta, bn_mean, bn_var);
    attn_kernel<<<dim3(4, BB * NHD), 224, ATTN_SMEM>>>(rpb);
    outup_kernel<<<dim3(16, BB), 224>>>(out);
}

// round 16
// speedup vs baseline: 1.1308x; 1.0484x over previous
#include <cuda_runtime.h>

#define BB   32
#define DIMC 512
#define CC   128
#define WSZ  14
#define NN   196
#define NHD  4
#define HD   32
#define HIN  56

typedef unsigned long long u64;

__device__ __forceinline__ u64 pk2(float lo, float hi) {
    u64 r; asm("mov.b64 %0, {%1, %2};" : "=l"(r) : "f"(lo), "f"(hi)); return r;
}
__device__ __forceinline__ u64 bc2(float v) { return pk2(v, v); }
__device__ __forceinline__ u64 ffma2(u64 a, u64 b, u64 c) {
    u64 d; asm("fma.rn.f32x2 %0, %1, %2, %3;" : "=l"(d) : "l"(a), "l"(b), "l"(c)); return d;
}
__device__ __forceinline__ u64 fmul2(u64 a, u64 b) {
    u64 d; asm("mul.rn.f32x2 %0, %1, %2;" : "=l"(d) : "l"(a), "l"(b)); return d;
}
__device__ __forceinline__ u64 fadd2(u64 a, u64 b) {
    u64 d; asm("add.rn.f32x2 %0, %1, %2;" : "=l"(d) : "l"(a), "l"(b)); return d;
}
__device__ __forceinline__ float2 upk2(u64 v) {
    float lo, hi; asm("mov.b64 {%0, %1}, %2;" : "=f"(lo), "=f"(hi) : "l"(v));
    float2 f; f.x = lo; f.y = hi; return f;
}

// Scratch (device globals; no runtime allocation)
__device__ float g_q[BB * NHD * NN * HD];  // [B][H][N][D] (pre-scaled via wT)
__device__ float g_k[BB * NHD * NN * HD];
__device__ float g_v[BB * NHD * NN * HD];
__device__ float g_ot[BB * CC * NN];       // attention output TRANSPOSED [B][C][N]
__device__ float g_wf[DIMC * CC];          // fused convout@proj weight [512][128]
__device__ float g_wfT[CC * DIMC];         // transposed fused weight [128][512]
__device__ float g_bf[DIMC];               // fused bias
__device__ float g_wqkvT[CC * 3 * CC];     // qkv weight transposed [c][j], q rows pre-scaled

// ---------------------------------------------------------------------------
// K0: prep. blocks 0..511: Wf = convout_w @ proj_w (+ transpose), bf
//          blocks 512..639: transpose qkv_w -> [c][j], q rows pre-scaled
// grid 640, block 384
// ---------------------------------------------------------------------------
__global__ void prep_kernel(const float* __restrict__ cw,
                            const float* __restrict__ cb,
                            const float* __restrict__ pw,
                            const float* __restrict__ pb,
                            const float* __restrict__ qkvw)
{
    int t = threadIdx.x;
    if (blockIdx.x < DIMC) {
        int oc = blockIdx.x;
        __shared__ float row[CC];
        __shared__ float red[CC];
        if (t < CC) row[t] = cw[oc * CC + t];
        __syncthreads();
        if (t < CC) {
            float acc = 0.0f;
            for (int k = 0; k < CC; k++) acc += row[k] * pw[k * CC + t];
            g_wf[oc * CC + t] = acc;
            g_wfT[t * DIMC + oc] = acc;
            red[t] = row[t] * pb[t];
        }
        __syncthreads();
        for (int s = 64; s > 0; s >>= 1) {
            if (t < s) red[t] += red[t + s];
            __syncthreads();
        }
        if (t == 0) g_bf[oc] = red[0] + cb[oc];
    } else {
        int c = blockIdx.x - DIMC;      // 0..127
        float v = qkvw[t * CC + c];
        if (t < CC) v *= 0.17677669529663687f;
        g_wqkvT[c * 384 + t] = v;
    }
}

// ---------------------------------------------------------------------------
// K1: FUSED grouped conv 4x4 s4 + BN + ReLU6 + qkv GEMM (f32x2 Phase 2).
// grid (7 token-tiles, B), block 448.
// ---------------------------------------------------------------------------
#define TS_STRIDE 132

__global__ void __launch_bounds__(448, 2)
convqkv_kernel(const float* __restrict__ x,
               const float* __restrict__ cw,
               const float* __restrict__ cb,
               const float* __restrict__ gamma,
               const float* __restrict__ beta,
               const float* __restrict__ mean,
               const float* __restrict__ var)
{
    __shared__ float ws[CC * 64];          // 32KB conv weights
    __shared__ float bnsc[CC], bnsh[CC];
    __shared__ float ts[28 * TS_STRIDE];   // token tile, padded

    int tile = blockIdx.x, b = blockIdx.y;
    int t = threadIdx.x;

    for (int idx = t; idx < CC * 64 / 4; idx += 448)
        ((float4*)ws)[idx] = ((const float4*)cw)[idx];
    if (t < CC) {
        float sc = gamma[t] * rsqrtf(var[t] + 1e-5f);
        bnsc[t] = sc;
        bnsh[t] = cb[t] * sc + beta[t] - mean[t] * sc;
    }
    __syncthreads();

    // ---- Phase 1: conv ----
    {
        int n = t % 28, cl = t / 28;       // cl 0..15
        int oh = tile * 2 + n / WSZ, ow = n % WSZ;
        const float* xb = x + (size_t)b * DIMC * HIN * HIN + (4 * oh) * HIN + 4 * ow;
#pragma unroll
        for (int p = 0; p < 8; p++) {
            int c = p * 16 + cl;
            float acc = 0.0f;
            const float* wp0 = ws + c * 64;
            const float* xc = xb + (size_t)(4 * c) * HIN * HIN;
#pragma unroll
            for (int i = 0; i < 4; i++) {
                const float* xp = xc + (size_t)i * HIN * HIN;
#pragma unroll
                for (int kh = 0; kh < 4; kh++) {
                    float4 v = *(const float4*)(xp + kh * HIN);
                    const float* wp = wp0 + i * 16 + kh * 4;
                    acc += v.x * wp[0] + v.y * wp[1] + v.z * wp[2] + v.w * wp[3];
                }
            }
            acc = acc * bnsc[c] + bnsh[c];
            ts[n * TS_STRIDE + c] = fminf(fmaxf(acc, 0.0f), 6.0f);
        }
    }
    __syncthreads();

    // ---- Phase 2: qkv GEMM, f32x2: acc packed over column pair (jp, jp+1) ----
    if (t < 384) {
        int jp = (t % 192) * 2;
        int rg = t / 192;
        int n0 = tile * 28;

        u64 accP[14];
#pragma unroll
        for (int r = 0; r < 14; r++) accP[r] = 0ull;

        const float* tsb = ts + (rg * 14) * TS_STRIDE;
        for (int cq = 0; cq < 32; cq++) {
            int c = cq * 4;
            u64 w0 = *(const u64*)(g_wqkvT + (size_t)(c + 0) * 384 + jp);
            u64 w1 = *(const u64*)(g_wqkvT + (size_t)(c + 1) * 384 + jp);
            u64 w2 = *(const u64*)(g_wqkvT + (size_t)(c + 2) * 384 + jp);
            u64 w3 = *(const u64*)(g_wqkvT + (size_t)(c + 3) * 384 + jp);
#pragma unroll
            for (int r = 0; r < 14; r++) {
                float4 tv = *(const float4*)(tsb + r * TS_STRIDE + c);
                u64 a = accP[r];
                a = ffma2(bc2(tv.x), w0, a);
                a = ffma2(bc2(tv.y), w1, a);
                a = ffma2(bc2(tv.z), w2, a);
                a = ffma2(bc2(tv.w), w3, a);
                accP[r] = a;
            }
        }

        float a0[14], a1[14];
#pragma unroll
        for (int r = 0; r < 14; r++) {
            float2 av = upk2(accP[r]);
            a0[r] = av.x; a1[r] = av.y;
        }

#pragma unroll
        for (int which = 0; which < 2; which++) {
            int j = jp + which;
            int s = j / CC, rem = j % CC;
            int h = rem / HD, d = rem % HD;
            float* dst = (s == 0) ? g_q : ((s == 1) ? g_k : g_v);
            dst += (((size_t)(b * NHD + h)) * NN + n0 + rg * 14) * HD + d;
            const float* a = which ? a1 : a0;
#pragma unroll
            for (int r = 0; r < 14; r++) dst[r * HD] = a[r];
        }
    }
}

// ---------------------------------------------------------------------------
// K2: attention (f32x2 QK + PV). grid (4 q-tiles, 128 bh), block 224.
// ---------------------------------------------------------------------------
#define KV_STRIDE 36
#define ATTN_SMEM ((196 * KV_STRIDE * 2 + 729) * 4)

__global__ void attn_kernel(const float* __restrict__ rpb)
{
    extern __shared__ float sm[];
    float* ks_s  = sm;
    float* vs_s  = sm + 196 * KV_STRIDE;
    float* rpb_s = sm + 196 * KV_STRIDE * 2;

    int qt = blockIdx.x;
    int bh = blockIdx.y;
    int h  = bh & 3;
    int t  = threadIdx.x;
    int qi = t >> 2, ks = t & 3;
    bool active = (qi < 49);
    int q = active ? (qt * 49 + qi) : 195;

    const float* kb = g_k + (size_t)bh * NN * HD;
    const float* vb = g_v + (size_t)bh * NN * HD;
    for (int idx = t; idx < 196 * 8; idx += 224) {
        int r = idx >> 3, qd = idx & 7;
        *(float4*)(ks_s + r * KV_STRIDE + qd * 4) = ((const float4*)(kb + r * HD))[qd];
        *(float4*)(vs_s + r * KV_STRIDE + qd * 4) = ((const float4*)(vb + r * HD))[qd];
    }
    for (int i = t; i < 729; i += 224) rpb_s[i] = rpb[i * NHD + h];
    __syncthreads();

    u64 q2[16];
    {
        const u64* qp = (const u64*)(g_q + ((size_t)bh * NN + q) * HD);
#pragma unroll
        for (int i = 0; i < 16; i++) q2[i] = qp[i];
    }
    int r1 = q / WSZ, c1 = q % WSZ;

    float mx = -1e30f, sum = 0.0f;
    u64 accP[16];
#pragma unroll
    for (int i = 0; i < 16; i++) accP[i] = 0ull;

    int base_m = ks * 49;
    for (int g = 0; g < 7; g++) {
        int m0 = base_m + g * 7;
        float s[7];
#pragma unroll
        for (int u = 0; u < 7; u++) {
            const u64* kr2 = (const u64*)(ks_s + (m0 + u) * KV_STRIDE);
            u64 sa = 0ull, sb = 0ull;
#pragma unroll
            for (int p = 0; p < 8; p++) {
                sa = ffma2(q2[2 * p + 0], kr2[2 * p + 0], sa);
                sb = ffma2(q2[2 * p + 1], kr2[2 * p + 1], sb);
            }
            float2 sv = upk2(fadd2(sa, sb));
            int m = m0 + u;
            int r2 = m / WSZ, c2 = m % WSZ;
            s[u] = sv.x + sv.y + rpb_s[(r1 - r2 + 13) * 27 + (c1 - c2 + 13)];
        }
        float gm = s[0];
#pragma unroll
        for (int u = 1; u < 7; u++) gm = fmaxf(gm, s[u]);
        float nm = fmaxf(mx, gm);
        float corr = __expf(mx - nm);
        mx = nm;
        float ps = 0.0f;
#pragma unroll
        for (int u = 0; u < 7; u++) { s[u] = __expf(s[u] - nm); ps += s[u]; }
        sum = sum * corr + ps;

        u64 corrP = bc2(corr);
        u64 sP[7];
#pragma unroll
        for (int u = 0; u < 7; u++) sP[u] = bc2(s[u]);

#pragma unroll
        for (int qd = 0; qd < 8; qd++) {
            u64 a0 = fmul2(accP[qd * 2 + 0], corrP);
            u64 a1 = fmul2(accP[qd * 2 + 1], corrP);
#pragma unroll
            for (int u = 0; u < 7; u++) {
                const u64* vr = (const u64*)(vs_s + (m0 + u) * KV_STRIDE + qd * 4);
                a0 = ffma2(sP[u], vr[0], a0);
                a1 = ffma2(sP[u], vr[1], a1);
            }
            accP[qd * 2 + 0] = a0;
            accP[qd * 2 + 1] = a1;
        }
    }

    float acc[32];
#pragma unroll
    for (int i = 0; i < 16; i++) {
        float2 f = upk2(accP[i]);
        acc[i * 2 + 0] = f.x;
        acc[i * 2 + 1] = f.y;
    }

#pragma unroll
    for (int off = 1; off <= 2; off <<= 1) {
        float m2 = __shfl_xor_sync(0xffffffffu, mx, off);
        float s2 = __shfl_xor_sync(0xffffffffu, sum, off);
        float nm = fmaxf(mx, m2);
        float ca = __expf(mx - nm);
        float cb2 = __expf(m2 - nm);
        sum = sum * ca + s2 * cb2;
#pragma unroll
        for (int d = 0; d < 32; d++)
            acc[d] = acc[d] * ca + __shfl_xor_sync(0xffffffffu, acc[d], off) * cb2;
        mx = nm;
    }

    if (active) {
        float inv = 1.0f / sum;
        int b = bh >> 2;
#pragma unroll
        for (int jj = 0; jj < 8; jj++) {
            int c = h * HD + ks * 8 + jj;
            g_ot[((size_t)b * CC + c) * NN + q] = acc[ks * 8 + jj] * inv;
        }
    }
}

// ---------------------------------------------------------------------------
// K3: fused (proj∘convout) GEMM (f32x2) + bilinear x4 upsample, writes d_out.
// grid (16 oc-tiles, B), block 224.
// Phase A (t<196): acc packed over oc-pairs; weights from transposed tile
//   (float4 smem load bit-reinterprets to two packed pairs, zero movs);
//   token values broadcast-packed. 16 FFMA2 per (thread, c).
// Phase B: separable upsample, two passes, colexp[32] regs, compile-time
//   row coefficients (unchanged from R14).
// ---------------------------------------------------------------------------
#define MS_STRIDE 197

__global__ void outup_kernel(float* __restrict__ out)
{
    __shared__ float wfsT[CC * 32];      // 16KB transposed weight tile [c][32 oc]
    __shared__ float bfs[32];
    __shared__ float ms[32 * MS_STRIDE]; // ~24.6KB
    __shared__ int   lo_s[HIN];
    __shared__ float w_s[HIN];

    int b = blockIdx.y;
    int oc0 = blockIdx.x * 32;
    int t = threadIdx.x;

    for (int idx = t; idx < CC * 8; idx += 224) {
        int c = idx >> 3, qv = idx & 7;
        ((float4*)wfsT)[c * 8 + qv] =
            *(const float4*)(g_wfT + (size_t)c * DIMC + oc0 + qv * 4);
    }
    if (t < 32) bfs[t] = g_bf[oc0 + t];
    if (t < HIN) {
        float s = (float)(t * 13) / 55.0f;
        int lo = (int)s;
        lo_s[t] = lo;
        w_s[t] = s - (float)lo;
    }
    __syncthreads();

    // Phase A: GEMM (thread = 4 tokens x 8 oc, packed over oc pairs)
    if (t < 196) {
        int ng = t % 49, ocg = t / 49;
        int n0 = ng * 4;
        u64 accP[16];   // [kp 0..3][tok 0..3]
#pragma unroll
        for (int i = 0; i < 16; i++) accP[i] = 0ull;

        const float* ob = g_ot + (size_t)b * CC * NN;
        for (int c = 0; c < CC; c++) {
            float4 ov = *(const float4*)(ob + (size_t)c * NN + n0);
            u64 ovb0 = bc2(ov.x), ovb1 = bc2(ov.y), ovb2 = bc2(ov.z), ovb3 = bc2(ov.w);
            const u64* wrow = (const u64*)(wfsT + c * 32 + ocg * 8);
#pragma unroll
            for (int kp = 0; kp < 4; kp++) {
                u64 w = wrow[kp];
                accP[kp * 4 + 0] = ffma2(w, ovb0, accP[kp * 4 + 0]);
                accP[kp * 4 + 1] = ffma2(w, ovb1, accP[kp * 4 + 1]);
                accP[kp * 4 + 2] = ffma2(w, ovb2, accP[kp * 4 + 2]);
                accP[kp * 4 + 3] = ffma2(w, ovb3, accP[kp * 4 + 3]);
            }
        }
#pragma unroll
        for (int kp = 0; kp < 4; kp++) {
            int k0 = ocg * 8 + kp * 2;
            float b0 = bfs[k0], b1 = bfs[k0 + 1];
#pragma unroll
            for (int tok = 0; tok < 4; tok++) {
                float2 f = upk2(accP[kp * 4 + tok]);
                ms[(k0 + 0) * MS_STRIDE + n0 + tok] = f.x + b0;
                ms[(k0 + 1) * MS_STRIDE + n0 + tok] = f.y + b1;
            }
        }
    }
    __syncthreads();

    // Phase B: separable upsample, two half-passes (colexp stays 32 regs)
    {
        int f  = t % 14;            // float4 index within output row (fixed)
        int cg = t / 14;            // 0..15 -> channels cg, cg+16

        int   lcz[4], hcz[4];
        float wcz[4];
#pragma unroll
        for (int z = 0; z < 4; z++) {
            int P = f * 4 + z;
            int lc = lo_s[P];
            lcz[z] = lc;
            hcz[z] = (lc + 1 < 14) ? lc + 1 : 13;
            wcz[z] = w_s[P];
        }

        float* obb = out + ((size_t)b * DIMC + oc0) * HIN * HIN;
#pragma unroll
        for (int cc2 = 0; cc2 < 2; cc2++) {
            int ch = cg + cc2 * 16;
            const float* src = ms + ch * MS_STRIDE;
            float* ocb = obb + (size_t)ch * (HIN * HIN) + f * 4;

#pragma unroll
            for (int pass = 0; pass < 2; pass++) {
                const int jbase = pass ? 6 : 0;

                float colexp[32];
#pragma unroll
                for (int j = 0; j < 8; j++) {
                    const float* sr = src + (jbase + j) * WSZ;
#pragma unroll
                    for (int z = 0; z < 4; z++) {
                        float a  = sr[lcz[z]];
                        float bq = sr[hcz[z]];
                        colexp[j * 4 + z] = a + wcz[z] * (bq - a);
                    }
                }

                const int Obase = pass * 28;
#pragma unroll
                for (int oo = 0; oo < 28; oo++) {
                    const int O  = Obase + oo;
                    const int lr = (O * 13) / 55;
                    const int hr = (lr + 1 < 14) ? lr + 1 : 13;
                    const float wr = (float)(O * 13 - lr * 55) * (1.0f / 55.0f);
                    const int lri = lr - jbase;
                    const int hri = hr - jbase;
                    float4 v;
#pragma unroll
                    for (int z = 0; z < 4; z++) {
                        float a  = colexp[lri * 4 + z];
                        float bq = colexp[hri * 4 + z];
                        ((float*)&v)[z] = a + wr * (bq - a);
                    }
                    *(float4*)(ocb + O * HIN) = v;
                }
            }
        }
    }
}

// ---------------------------------------------------------------------------
extern "C" void kernel_launch(void* const* d_in, const int* in_sizes, int n_in,
                              void* d_out, int out_size)
{
    (void)in_sizes; (void)n_in; (void)out_size;
    const float* x        = (const float*)d_in[0];
    const float* conv_w   = (const float*)d_in[1];
    const float* conv_b   = (const float*)d_in[2];
    const float* bn_gamma = (const float*)d_in[3];
    const float* bn_beta  = (const float*)d_in[4];
    const float* bn_mean  = (const float*)d_in[5];
    const float* bn_var   = (const float*)d_in[6];
    const float* qkv_w    = (const float*)d_in[7];
    const float* proj_w   = (const float*)d_in[8];
    const float* proj_b   = (const float*)d_in[9];
    const float* rpb      = (const float*)d_in[10];
    const float* cvo_w    = (const float*)d_in[11];
    const float* cvo_b    = (const float*)d_in[12];
    float* out = (float*)d_out;

    cudaFuncSetAttribute(attn_kernel, cudaFuncAttributeMaxDynamicSharedMemorySize, ATTN_SMEM);

    prep_kernel<<<DIMC + CC, 384>>>(cvo_w, cvo_b, proj_w, proj_b, qkv_w);
    convqkv_kernel<<<dim3(7, BB), 448>>>(x, conv_w, conv_b, bn_gamma, bn_beta, bn_mean, bn_var);
    attn_kernel<<<dim3(4, BB * NHD), 224, ATTN_SMEM>>>(rpb);
    outup_kernel<<<dim3(16, BB), 224>>>(out);
}